// round 14
// baseline (speedup 1.0000x reference)
#include <cuda_runtime.h>
#include <cuda_fp16.h>
#include <math.h>
#include <stdint.h>

// ---------------- problem constants ----------------
#define BB 4
#define TT 2048
#define DD 1024
#define HH 16
#define DKV 64
#define RR 64
#define KSZ 4
#define BH (BB*HH)      // 64
#define MTOK (BB*TT)    // 8192
#define EPSF 1e-6f

// ---------------- scratch (no cudaMalloc allowed) ----------------
__device__ __half g_qx[MTOK*DD];
__device__ __half g_kx[MTOK*DD];
__device__ __half g_vx[MTOK*DD];
__device__ __half g_og[MTOK*DD];
__device__ __half g_wq[DD*DD];
__device__ __half g_wk[DD*DD];
__device__ __half g_wv[DD*DD];
__device__ __half g_wo[DD*DD];
__device__ float g_Q [MTOK*DD];
__device__ float g_K [MTOK*DD];
__device__ float g_V [MTOK*DD];
__device__ float g_alpha[MTOK*DD];
__device__ float g_O [MTOK*DD];
__device__ float g_hidA[MTOK*RR];
__device__ float g_hidG[MTOK*RR];
__device__ float g_beta[MTOK*HH];
__device__ float g_gate[MTOK*HH];

__device__ __forceinline__ float sigmoidf_(float v){ return 1.0f/(1.0f+expf(-v)); }
__device__ __forceinline__ float siluf_(float v){ return v/(1.0f+expf(-v)); }

// ---------------- PTX helpers (baseline ISA only; NO sm_100a features) -------------
__device__ __forceinline__ uint32_t smem_u32(const void* p){
    uint32_t a;
    asm("{ .reg .u64 t; cvta.to.shared.u64 t, %1; cvt.u32.u64 %0, t; }" : "=r"(a) : "l"(p));
    return a;
}
#define CP_COMMIT() asm volatile("cp.async.commit_group;" ::: "memory")
#define CP_WAIT1()  asm volatile("cp.async.wait_group 1;" ::: "memory")
__device__ __forceinline__ void cp16(uint32_t dst, const void* src){
    asm volatile("cp.async.cg.shared.global [%0], [%1], 16;" :: "r"(dst), "l"(src) : "memory");
}
__device__ __forceinline__ void ldm4(uint32_t* r, uint32_t addr){
    asm volatile("ldmatrix.sync.aligned.m8n8.x4.shared.b16 {%0,%1,%2,%3}, [%4];"
        : "=r"(r[0]), "=r"(r[1]), "=r"(r[2]), "=r"(r[3]) : "r"(addr));
}
__device__ __forceinline__ void mma16816(float* d, const uint32_t* a, const uint32_t* b){
    asm volatile("mma.sync.aligned.m16n8k16.row.col.f32.f16.f16.f32 "
        "{%0,%1,%2,%3}, {%4,%5,%6,%7}, {%8,%9}, {%0,%1,%2,%3};"
        : "+f"(d[0]), "+f"(d[1]), "+f"(d[2]), "+f"(d[3])
        : "r"(a[0]), "r"(a[1]), "r"(a[2]), "r"(a[3]), "r"(b[0]), "r"(b[1]));
}

// ---------------- conv + SiLU -> fp16 ----------------
__global__ void conv_silu_f16(const float* __restrict__ x,
                              const float* __restrict__ wq, const float* __restrict__ bq,
                              const float* __restrict__ wk, const float* __restrict__ bk,
                              const float* __restrict__ wv, const float* __restrict__ bv)
{
    int idx = blockIdx.x*blockDim.x + threadIdx.x;
    if (idx >= MTOK*DD) return;
    int d = idx % DD;
    int t = (idx / DD) % TT;
    int b = idx / (DD*TT);

    float xs[KSZ];
#pragma unroll
    for (int j = 0; j < KSZ; j++) {
        int tt = t - (KSZ-1) + j;
        xs[j] = (tt >= 0) ? x[((size_t)b*TT + tt)*DD + d] : 0.0f;
    }
    float aq = bq[d], ak = bk[d], av = bv[d];
#pragma unroll
    for (int j = 0; j < KSZ; j++) {
        aq = fmaf(xs[j], wq[d*KSZ + j], aq);
        ak = fmaf(xs[j], wk[d*KSZ + j], ak);
        av = fmaf(xs[j], wv[d*KSZ + j], av);
    }
    g_qx[idx] = __float2half_rn(siluf_(aq));
    g_kx[idx] = __float2half_rn(siluf_(ak));
    g_vx[idx] = __float2half_rn(siluf_(av));
}

// ---------------- 4 weights: [K,N] f32 -> [N,K] fp16 (one launch) ------------------
__global__ void wsplit_all(const float* __restrict__ W0, __half* __restrict__ H0,
                           const float* __restrict__ W1, __half* __restrict__ H1,
                           const float* __restrict__ W2, __half* __restrict__ H2,
                           const float* __restrict__ W3, __half* __restrict__ H3)
{
    const float* W; __half* Th;
    switch (blockIdx.z) {
        case 0: W = W0; Th = H0; break;
        case 1: W = W1; Th = H1; break;
        case 2: W = W2; Th = H2; break;
        default: W = W3; Th = H3; break;
    }
    __shared__ float tile[32][33];
    int k = blockIdx.y*32 + threadIdx.y;
    int n = blockIdx.x*32 + threadIdx.x;
    tile[threadIdx.y][threadIdx.x] = W[(size_t)k*DD + n];
    __syncthreads();
    int n2 = blockIdx.x*32 + threadIdx.y;
    int k2 = blockIdx.y*32 + threadIdx.x;
    Th[(size_t)n2*DD + k2] = __float2half_rn(tile[threadIdx.x][threadIdx.y]);
}

// ---------------- HMMA fp16 single-pass GEMM core ----------------------------------
#define STAGES 3
#define AROWB 80
#define STAGE_A_BYTES (128*AROWB)
#define STAGE_BYTES   (2*STAGE_A_BYTES)
#define HG_SMEM       (STAGES*STAGE_BYTES)   // 61440
#define HG_NIT 32

__device__ __forceinline__ void hgemm_body(
    const __half* __restrict__ Ap, const __half* __restrict__ Bp,
    const float* __restrict__ bias, float* __restrict__ C, int N_,
    bool do_l2, char* smem, int m0, int n0)
{
    uint32_t sb = smem_u32(smem);
    const int tid = threadIdx.x;
    const int wid = tid >> 5, lane = tid & 31;
    const int warp_m = wid >> 2, warp_n = wid & 3;

    float acc[4][4][4];
#pragma unroll
    for (int i = 0; i < 4; i++)
#pragma unroll
        for (int j = 0; j < 4; j++)
#pragma unroll
            for (int k = 0; k < 4; k++) acc[i][j][k] = 0.0f;

    const int lrow = tid >> 1;
    const int lcb  = (tid & 1) * 2;

    auto load_stage = [&](int it) {
        int kk = it << 5;
        uint32_t st = sb + (uint32_t)(it % STAGES) * STAGE_BYTES;
        const __half* ga = Ap + (size_t)(m0 + lrow)*DD + kk + lcb*8;
        uint32_t da = st + lrow*AROWB + lcb*16;
        cp16(da,      ga);
        cp16(da + 16, ga + 8);
        const __half* gb = Bp + (size_t)(n0 + lrow)*DD + kk + lcb*8;
        uint32_t db = st + STAGE_A_BYTES + lrow*AROWB + lcb*16;
        cp16(db,      gb);
        cp16(db + 16, gb + 8);
        CP_COMMIT();
    };

    load_stage(0); load_stage(1);

    const uint32_t a_row = warp_m*64 + (lane & 15);
    const uint32_t a_col = (lane >> 4) * 16;
    const uint32_t b_row = warp_n*32 + (lane & 7) + ((lane >> 4) & 1) * 8;
    const uint32_t b_col = ((lane >> 3) & 1) * 16;

    for (int i = 0; i < HG_NIT; i++) {
        CP_WAIT1();
        __syncthreads();
        int j = i + 2;
        if (j < HG_NIT) load_stage(j); else CP_COMMIT();

        uint32_t st = sb + (uint32_t)(i % STAGES) * STAGE_BYTES;
#pragma unroll
        for (int ks = 0; ks < 2; ks++) {
            uint32_t afr[4][4], bfr[2][4];
            uint32_t abase = st + a_row*AROWB + ks*32 + a_col;
#pragma unroll
            for (int mf = 0; mf < 4; mf++) ldm4(afr[mf], abase + mf*(16*AROWB));
            uint32_t bbase = st + STAGE_A_BYTES + b_row*AROWB + ks*32 + b_col;
#pragma unroll
            for (int np = 0; np < 2; np++) ldm4(bfr[np], bbase + np*(16*AROWB));
#pragma unroll
            for (int mf = 0; mf < 4; mf++)
#pragma unroll
                for (int nf = 0; nf < 4; nf++)
                    mma16816(acc[mf][nf], afr[mf], &bfr[nf >> 1][(nf & 1) * 2]);
        }
    }

    const int trow = lane >> 2, tcol = (lane & 3) * 2;

#pragma unroll
    for (int nf = 0; nf < 4; nf++) {
        int c = n0 + warp_n*32 + nf*8 + tcol;
        float b0 = bias[c], b1 = bias[c+1];
#pragma unroll
        for (int mf = 0; mf < 4; mf++) {
            acc[mf][nf][0] += b0; acc[mf][nf][1] += b1;
            acc[mf][nf][2] += b0; acc[mf][nf][3] += b1;
        }
    }

    if (do_l2) {
        float rs[8];
#pragma unroll
        for (int mf = 0; mf < 4; mf++) {
            float s0 = 0.f, s1 = 0.f;
#pragma unroll
            for (int nf = 0; nf < 4; nf++) {
                s0 = fmaf(acc[mf][nf][0], acc[mf][nf][0], s0);
                s0 = fmaf(acc[mf][nf][1], acc[mf][nf][1], s0);
                s1 = fmaf(acc[mf][nf][2], acc[mf][nf][2], s1);
                s1 = fmaf(acc[mf][nf][3], acc[mf][nf][3], s1);
            }
            rs[mf*2]   = s0;
            rs[mf*2+1] = s1;
        }
#pragma unroll
        for (int r = 0; r < 8; r++) {
            rs[r] += __shfl_xor_sync(0xFFFFFFFFu, rs[r], 1);
            rs[r] += __shfl_xor_sync(0xFFFFFFFFu, rs[r], 2);
        }
        __syncthreads();
        float* sred = reinterpret_cast<float*>(smem);   // [4][128]
        if ((lane & 3) == 0) {
#pragma unroll
            for (int mf = 0; mf < 4; mf++) {
                int r = warp_m*64 + mf*16 + trow;
                sred[warp_n*128 + r]     = rs[mf*2];
                sred[warp_n*128 + r + 8] = rs[mf*2+1];
            }
        }
        __syncthreads();
        const int gp = (warp_n >> 1) * 2;
#pragma unroll
        for (int mf = 0; mf < 4; mf++) {
#pragma unroll
            for (int half = 0; half < 2; half++) {
                int r = warp_m*64 + mf*16 + trow + half*8;
                float tot = sred[gp*128 + r] + sred[(gp+1)*128 + r];
                float rn = rsqrtf(fmaxf(tot, EPSF));
                acc[mf][0][half*2]   *= rn; acc[mf][0][half*2+1] *= rn;
                acc[mf][1][half*2]   *= rn; acc[mf][1][half*2+1] *= rn;
                acc[mf][2][half*2]   *= rn; acc[mf][2][half*2+1] *= rn;
                acc[mf][3][half*2]   *= rn; acc[mf][3][half*2+1] *= rn;
            }
        }
    }

#pragma unroll
    for (int mf = 0; mf < 4; mf++) {
        int r = m0 + warp_m*64 + mf*16 + trow;
#pragma unroll
        for (int nf = 0; nf < 4; nf++) {
            int c = n0 + warp_n*32 + nf*8 + tcol;
            float* p0 = C + (size_t)r*N_ + c;
            float* p1 = C + (size_t)(r+8)*N_ + c;
            p0[0] = acc[mf][nf][0]; p0[1] = acc[mf][nf][1];
            p1[0] = acc[mf][nf][2]; p1[1] = acc[mf][nf][3];
        }
    }
}

// single-matrix wrapper (output GEMM)
__global__ __launch_bounds__(256)
void hgemm1(const __half* __restrict__ Ap, const __half* __restrict__ Bp,
            const float* __restrict__ bias, float* __restrict__ C, int N_)
{
    extern __shared__ char smem[];
    hgemm_body(Ap, Bp, bias, C, N_, false, smem, blockIdx.y << 7, blockIdx.x << 7);
}

// z-batched QKV GEMM: z=0 Q (L2), z=1 K (L2), z=2 V
__global__ __launch_bounds__(256)
void hgemm_qkv(const __half* __restrict__ qx, const __half* __restrict__ kx,
               const __half* __restrict__ vx,
               const __half* __restrict__ wq, const __half* __restrict__ wk,
               const __half* __restrict__ wv,
               const float* __restrict__ bq, const float* __restrict__ bk,
               const float* __restrict__ bv,
               float* __restrict__ Qp, float* __restrict__ Kp, float* __restrict__ Vp)
{
    extern __shared__ char smem[];
    const __half *Ap, *Bp; const float* bias; float* C; bool do_l2;
    switch (blockIdx.z) {
        case 0:  Ap = qx; Bp = wq; bias = bq; C = Qp; do_l2 = true;  break;
        case 1:  Ap = kx; Bp = wk; bias = bk; C = Kp; do_l2 = true;  break;
        default: Ap = vx; Bp = wv; bias = bv; C = Vp; do_l2 = false; break;
    }
    hgemm_body(Ap, Bp, bias, C, DD, do_l2, smem, blockIdx.y << 7, blockIdx.x << 7);
}

// ---------------- fp32 SGEMM 128x128 (alpha-up, K=64, sigmoid) ---------------------
template<int ACT>
__global__ __launch_bounds__(256)
void gemm128(const float* __restrict__ A, const float* __restrict__ W,
             const float* __restrict__ bias, float* __restrict__ C,
             int M, int N, int K)
{
    __shared__ float As[8][128];
    __shared__ float Bs[8][128];

    const int tid = threadIdx.x;
    const int m0 = blockIdx.y * 128;
    const int n0 = blockIdx.x * 128;
    const int ty = tid >> 4;
    const int tx = tid & 15;
    const int arow = tid >> 1;
    const int ak   = (tid & 1) * 4;
    const int brow = tid >> 5;
    const int bcol = (tid & 31) * 4;

    float acc[8][8];
#pragma unroll
    for (int i = 0; i < 8; i++)
#pragma unroll
        for (int j = 0; j < 8; j++) acc[i][j] = 0.0f;

    for (int k0 = 0; k0 < K; k0 += 8) {
        float4 a4 = *reinterpret_cast<const float4*>(&A[(size_t)(m0 + arow)*K + k0 + ak]);
        float4 b4 = *reinterpret_cast<const float4*>(&W[(size_t)(k0 + brow)*N + n0 + bcol]);
        __syncthreads();
        As[ak+0][arow] = a4.x; As[ak+1][arow] = a4.y;
        As[ak+2][arow] = a4.z; As[ak+3][arow] = a4.w;
        *reinterpret_cast<float4*>(&Bs[brow][bcol]) = b4;
        __syncthreads();
#pragma unroll
        for (int k = 0; k < 8; k++) {
            float ra[8], rb[8];
#pragma unroll
            for (int i = 0; i < 8; i++) ra[i] = As[k][ty*8 + i];
#pragma unroll
            for (int i = 0; i < 8; i++) rb[i] = Bs[k][tx*8 + i];
#pragma unroll
            for (int i = 0; i < 8; i++)
#pragma unroll
                for (int j = 0; j < 8; j++)
                    acc[i][j] = fmaf(ra[i], rb[j], acc[i][j]);
        }
    }

#pragma unroll
    for (int i = 0; i < 8; i++) {
        int m = m0 + ty*8 + i;
#pragma unroll
        for (int j = 0; j < 8; j++) {
            int n = n0 + tx*8 + j;
            float c = acc[i][j] + bias[n];
            if (ACT == 1) c = siluf_(c);
            else if (ACT == 2) c = sigmoidf_(c);
            C[(size_t)m*N + n] = c;
        }
    }
}

// ---------------- fused x-projections: hA (silu) | hG (silu) | beta (sigmoid) ------
__global__ __launch_bounds__(256)
void prep144(const float* __restrict__ x,
             const float* __restrict__ W_ad, const float* __restrict__ b_ad,
             const float* __restrict__ W_gd, const float* __restrict__ b_gd,
             const float* __restrict__ W_bt, const float* __restrict__ b_bt,
             float* __restrict__ hA, float* __restrict__ hG, float* __restrict__ Bt)
{
    __shared__ float Xs[16][68];
    __shared__ float Ws[16][144];

    const int tid = threadIdx.x;
    const int m0 = blockIdx.x * 64;
    const int ty = tid >> 4, tx = tid & 15;

    float acc[4][9];
#pragma unroll
    for (int i = 0; i < 4; i++)
#pragma unroll
        for (int j = 0; j < 9; j++) acc[i][j] = 0.0f;

    const int xrow = tid >> 2, xk = (tid & 3) * 4;
    const int wk = tid >> 4, wc = tid & 15;

    for (int k0 = 0; k0 < DD; k0 += 16) {
        __syncthreads();
        float4 xv = *reinterpret_cast<const float4*>(&x[(size_t)(m0 + xrow)*DD + k0 + xk]);
        Xs[xk+0][xrow] = xv.x; Xs[xk+1][xrow] = xv.y;
        Xs[xk+2][xrow] = xv.z; Xs[xk+3][xrow] = xv.w;
#pragma unroll
        for (int j = 0; j < 9; j++) {
            int c = wc + j*16;
            float w;
            if (c < 64)       w = W_ad[(size_t)(k0 + wk)*64 + c];
            else if (c < 128) w = W_gd[(size_t)(k0 + wk)*64 + (c - 64)];
            else              w = W_bt[(size_t)(k0 + wk)*16 + (c - 128)];
            Ws[wk][c] = w;
        }
        __syncthreads();
#pragma unroll
        for (int k = 0; k < 16; k++) {
            float ra[4], rb[9];
#pragma unroll
            for (int i = 0; i < 4; i++) ra[i] = Xs[k][ty*4 + i];
#pragma unroll
            for (int j = 0; j < 9; j++) rb[j] = Ws[k][tx + j*16];
#pragma unroll
            for (int i = 0; i < 4; i++)
#pragma unroll
                for (int j = 0; j < 9; j++)
                    acc[i][j] = fmaf(ra[i], rb[j], acc[i][j]);
        }
    }

#pragma unroll
    for (int i = 0; i < 4; i++) {
        int m = m0 + ty*4 + i;
#pragma unroll
        for (int j = 0; j < 9; j++) {
            int c = tx + j*16;
            float v = acc[i][j];
            if (c < 64)       hA[(size_t)m*64 + c]        = siluf_(v + b_ad[c]);
            else if (c < 128) hG[(size_t)m*64 + (c-64)]   = siluf_(v + b_gd[c-64]);
            else              Bt[(size_t)m*16 + (c-128)]  = sigmoidf_(v + b_bt[c-128]);
        }
    }
}

// ---------------- gate-up: gate = sigmoid(hidG @ W_gu + b_gu) ----------------------
__global__ __launch_bounds__(256)
void gateup(const float* __restrict__ hG, const float* __restrict__ W_gu,
            const float* __restrict__ b_gu, float* __restrict__ Gt)
{
    int gidx = blockIdx.x*256 + threadIdx.x;
    int m = gidx >> 4, h = gidx & 15;
    const float* row = hG + (size_t)m*64;
    float s = b_gu[h];
#pragma unroll 8
    for (int i = 0; i < 64; i++) s = fmaf(row[i], W_gu[i*16 + h], s);
    Gt[gidx] = sigmoidf_(s);
}

// ---------------- gated delta-rule scan v10: w=16 + deep k/a prefetch --------------
// 256 blocks = (head, col-quarter), 256 thr: e=tid&15 -> 4 rows, col=qtr*16+(tid>>4).
// k/a (recurrence-critical) ring-8/distance-7; q/v/beta (o-path) ring-4/distance-3.
// ~115 regs -> still 2 blocks/SM. Deferred o-reduction per 8 steps (R10 arithmetic).
__global__ __launch_bounds__(256)
void scan_kernel10(const float* __restrict__ Q, const float* __restrict__ K,
                   const float* __restrict__ V, const float* __restrict__ A,
                   const float* __restrict__ Beta,
                   float* __restrict__ O, float* __restrict__ Sout)
{
    const int blk = blockIdx.x;           // 0..255
    const int bh  = blk >> 2, qtr = blk & 3;
    const int b = bh / HH, h = bh % HH;
    const int tid = threadIdx.x;
    const int e   = tid & 15;
    const int col = qtr*16 + (tid >> 4);
    const int r0  = e * 4;

    const size_t base  = ((size_t)b*TT)*DD + (size_t)h*64;
    const size_t bbase = (size_t)b*TT*HH + h;

    float S[4];
#pragma unroll
    for (int i = 0; i < 4; i++) S[i] = 0.0f;

    float4 kb[8], ab[8];     // deep ring (recurrence operands)
    float4 qb[4];            // shallow ring (output operands)
    float  vb[4], bbuf[4];

#define LOAD_KA(t_, s_) do { \
    kb[s_] = *reinterpret_cast<const float4*>(K + base + (size_t)(t_)*DD + r0); \
    ab[s_] = *reinterpret_cast<const float4*>(A + base + (size_t)(t_)*DD + r0); \
} while(0)
#define LOAD_QVB(t_, s_) do { \
    qb[s_] = *reinterpret_cast<const float4*>(Q + base + (size_t)(t_)*DD + r0); \
    vb[s_]   = V[base + (size_t)(t_)*DD + col]; \
    bbuf[s_] = Beta[bbase + (size_t)(t_)*HH]; \
} while(0)

#pragma unroll
    for (int t = 0; t < 7; t++) LOAD_KA(t, t);
#pragma unroll
    for (int t = 0; t < 3; t++) LOAD_QVB(t, t);

    for (int g = 0; g < TT/8; g++) {
        float ob[8];
#pragma unroll
        for (int u = 0; u < 8; u++) {
            const int t = g*8 + u;
            // all ring slots compile-time: t%8==u, (t+7)%8==(u+7)&7, (t+3)%4==(u+3)&3
            if (t + 7 < TT) LOAD_KA(t + 7, (u + 7) & 7);
            if (t + 3 < TT) LOAD_QVB(t + 3, (u + 3) & 3);

            float k_[4], a_[4], q_[4];
            *reinterpret_cast<float4*>(k_) = kb[u];
            *reinterpret_cast<float4*>(a_) = ab[u];
            *reinterpret_cast<float4*>(q_) = qb[u & 3];
            const float vv = vb[u & 3];
            const float bt = bbuf[u & 3];

            float p0 = 0.f, p1 = 0.f;
            S[0] *= a_[0]; p0 = fmaf(k_[0], S[0], p0);
            S[1] *= a_[1]; p1 = fmaf(k_[1], S[1], p1);
            S[2] *= a_[2]; p0 = fmaf(k_[2], S[2], p0);
            S[3] *= a_[3]; p1 = fmaf(k_[3], S[3], p1);
            float p = p0 + p1;
            p += __shfl_xor_sync(0xFFFFFFFFu, p, 1);
            p += __shfl_xor_sync(0xFFFFFFFFu, p, 2);
            p += __shfl_xor_sync(0xFFFFFFFFu, p, 4);
            p += __shfl_xor_sync(0xFFFFFFFFu, p, 8);

            float c = bt * (vv - p);

            float o0 = 0.f, o1 = 0.f;
            S[0] = fmaf(k_[0], c, S[0]); o0 = fmaf(S[0], q_[0], o0);
            S[1] = fmaf(k_[1], c, S[1]); o1 = fmaf(S[1], q_[1], o1);
            S[2] = fmaf(k_[2], c, S[2]); o0 = fmaf(S[2], q_[2], o0);
            S[3] = fmaf(k_[3], c, S[3]); o1 = fmaf(S[3], q_[3], o1);
            ob[u] = o0 + o1;
        }

#pragma unroll
        for (int r = 1; r <= 8; r <<= 1) {
            float t0 = __shfl_xor_sync(0xFFFFFFFFu, ob[0], r);
            float t1 = __shfl_xor_sync(0xFFFFFFFFu, ob[1], r);
            float t2 = __shfl_xor_sync(0xFFFFFFFFu, ob[2], r);
            float t3 = __shfl_xor_sync(0xFFFFFFFFu, ob[3], r);
            float t4 = __shfl_xor_sync(0xFFFFFFFFu, ob[4], r);
            float t5 = __shfl_xor_sync(0xFFFFFFFFu, ob[5], r);
            float t6 = __shfl_xor_sync(0xFFFFFFFFu, ob[6], r);
            float t7 = __shfl_xor_sync(0xFFFFFFFFu, ob[7], r);
            ob[0] += t0; ob[1] += t1; ob[2] += t2; ob[3] += t3;
            ob[4] += t4; ob[5] += t5; ob[6] += t6; ob[7] += t7;
        }
        if (e == 0) {
            const int tg = g * 8;
#pragma unroll
            for (int u = 0; u < 8; u++)
                O[base + (size_t)(tg + u)*DD + col] = ob[u];
        }
    }
#undef LOAD_KA
#undef LOAD_QVB

#pragma unroll
    for (int i = 0; i < 4; i++)
        Sout[(size_t)bh*DKV*DKV + (size_t)(r0 + i)*DKV + col] = S[i];
}

// ---------------- headwise RMSNorm + gate -> fp16 ----------------------------------
__global__ __launch_bounds__(256)
void normgate_f16(const float* __restrict__ O, const float* __restrict__ rms_w,
                  const float* __restrict__ gate, __half* __restrict__ og)
{
    int row = blockIdx.x*4 + (threadIdx.x >> 6);
    int j   = threadIdx.x & 63;
    int h   = row % HH;

    float v = O[(size_t)row*64 + j];
    float ss = v*v;
#pragma unroll
    for (int o = 16; o; o >>= 1) ss += __shfl_xor_sync(0xFFFFFFFFu, ss, o);

    __shared__ float part[8];
    if ((threadIdx.x & 31) == 0) part[threadIdx.x >> 5] = ss;
    __syncthreads();
    int w0 = (threadIdx.x >> 6) * 2;
    float tot = part[w0] + part[w0 + 1];

    float rn  = rsqrtf(tot * (1.0f/64.0f) + EPSF);
    og[(size_t)row*64 + j] = __float2half_rn(v * rn * rms_w[h*64 + j] * gate[row]);
}

// ---------------- launch (multi-stream fork/join, graph-capturable) ----------------
extern "C" void kernel_launch(void* const* d_in, const int* in_sizes, int n_in,
                              void* d_out, int out_size)
{
    const float* x       = (const float*)d_in[0];
    const float* conv_qw = (const float*)d_in[1];
    const float* conv_qb = (const float*)d_in[2];
    const float* conv_kw = (const float*)d_in[3];
    const float* conv_kb = (const float*)d_in[4];
    const float* conv_vw = (const float*)d_in[5];
    const float* conv_vb = (const float*)d_in[6];
    const float* Wq      = (const float*)d_in[7];
    const float* bq      = (const float*)d_in[8];
    const float* Wk      = (const float*)d_in[9];
    const float* bk      = (const float*)d_in[10];
    const float* Wv      = (const float*)d_in[11];
    const float* bv      = (const float*)d_in[12];
    const float* W_ad    = (const float*)d_in[13];
    const float* b_ad    = (const float*)d_in[14];
    const float* W_au    = (const float*)d_in[15];
    const float* b_au    = (const float*)d_in[16];
    const float* W_beta  = (const float*)d_in[17];
    const float* b_beta  = (const float*)d_in[18];
    const float* rms_w   = (const float*)d_in[19];
    const float* W_gd    = (const float*)d_in[20];
    const float* b_gd    = (const float*)d_in[21];
    const float* W_gu    = (const float*)d_in[22];
    const float* b_gu    = (const float*)d_in[23];
    const float* Wo      = (const float*)d_in[24];
    const float* bo      = (const float*)d_in[25];

    float* out = (float*)d_out;
    float* y = out;
    const size_t y_elems = (size_t)MTOK * DD;
    const size_t s_elems = (size_t)BH * DKV * DKV;
    float* Sout = out + ((size_t)out_size >= y_elems + s_elems
                         ? (size_t)out_size - s_elems : y_elems);

    float *Qp, *Kp, *Vp, *Al, *Op, *hA, *hG, *Bt, *Gt;
    cudaGetSymbolAddress((void**)&Qp, g_Q);
    cudaGetSymbolAddress((void**)&Kp, g_K);
    cudaGetSymbolAddress((void**)&Vp, g_V);
    cudaGetSymbolAddress((void**)&Al, g_alpha);
    cudaGetSymbolAddress((void**)&Op, g_O);
    cudaGetSymbolAddress((void**)&hA, g_hidA);
    cudaGetSymbolAddress((void**)&hG, g_hidG);
    cudaGetSymbolAddress((void**)&Bt, g_beta);
    cudaGetSymbolAddress((void**)&Gt, g_gate);

    __half *qx,*kx,*vx,*og,*wq,*wk,*wv,*wo;
    cudaGetSymbolAddress((void**)&qx, g_qx);
    cudaGetSymbolAddress((void**)&kx, g_kx);
    cudaGetSymbolAddress((void**)&vx, g_vx);
    cudaGetSymbolAddress((void**)&og, g_og);
    cudaGetSymbolAddress((void**)&wq, g_wq);
    cudaGetSymbolAddress((void**)&wk, g_wk);
    cudaGetSymbolAddress((void**)&wv, g_wv);
    cudaGetSymbolAddress((void**)&wo, g_wo);

    cudaFuncSetAttribute(hgemm1,    cudaFuncAttributeMaxDynamicSharedMemorySize, HG_SMEM);
    cudaFuncSetAttribute(hgemm_qkv, cudaFuncAttributeMaxDynamicSharedMemorySize, HG_SMEM);

    static cudaStream_t s1 = nullptr, s2 = nullptr;
    static cudaEvent_t evRoot = nullptr, evW = nullptr, evAlpha = nullptr, evGate = nullptr;
    if (!s1) {
        cudaStreamCreateWithFlags(&s1, cudaStreamNonBlocking);
        cudaStreamCreateWithFlags(&s2, cudaStreamNonBlocking);
        cudaEventCreateWithFlags(&evRoot,  cudaEventDisableTiming);
        cudaEventCreateWithFlags(&evW,     cudaEventDisableTiming);
        cudaEventCreateWithFlags(&evAlpha, cudaEventDisableTiming);
        cudaEventCreateWithFlags(&evGate,  cudaEventDisableTiming);
    }

    cudaEventRecord(evRoot, 0);
    cudaStreamWaitEvent(s1, evRoot, 0);
    cudaStreamWaitEvent(s2, evRoot, 0);

    dim3 wgrid(DD/32, DD/32, 4), wblk(32, 32);
    wsplit_all<<<wgrid, wblk, 0, s1>>>(Wq, wq, Wk, wk, Wv, wv, Wo, wo);
    cudaEventRecord(evW, s1);

    prep144<<<MTOK/64, 256, 0, s2>>>(x, W_ad, b_ad, W_gd, b_gd, W_beta, b_beta, hA, hG, Bt);
    gemm128<2><<<dim3(DD/128, MTOK/128), 256, 0, s2>>>(hA, W_au, b_au, Al, MTOK, DD, RR);
    cudaEventRecord(evAlpha, s2);
    gateup<<<MTOK*HH/256, 256, 0, s2>>>(hG, W_gu, b_gu, Gt);
    cudaEventRecord(evGate, s2);

    conv_silu_f16<<<(MTOK*DD + 255)/256, 256>>>(x, conv_qw, conv_qb,
                                                conv_kw, conv_kb, conv_vw, conv_vb);
    cudaStreamWaitEvent(0, evW, 0);

    // Q/K/V projections in ONE z-batched launch
    dim3 tgrid3(DD/128, MTOK/128, 3);
    hgemm_qkv<<<tgrid3, 256, HG_SMEM>>>(qx, kx, vx, wq, wk, wv, bq, bk, bv, Qp, Kp, Vp);

    cudaStreamWaitEvent(0, evAlpha, 0);
    scan_kernel10<<<4*BH, 256>>>(Qp, Kp, Vp, Al, Bt, Op, Sout);

    cudaStreamWaitEvent(0, evGate, 0);
    normgate_f16<<<(MTOK*HH)/4, 256>>>(Op, rms_w, Gt, og);
    dim3 tgrid(DD/128, MTOK/128);
    hgemm1<<<tgrid, 256, HG_SMEM>>>(og, wo, bo, y, DD);
}

// round 15
// speedup vs baseline: 1.5088x; 1.5088x over previous
#include <cuda_runtime.h>
#include <cuda_fp16.h>
#include <math.h>
#include <stdint.h>

// ---------------- problem constants ----------------
#define BB 4
#define TT 2048
#define DD 1024
#define HH 16
#define DKV 64
#define RR 64
#define KSZ 4
#define BH (BB*HH)      // 64
#define MTOK (BB*TT)    // 8192
#define EPSF 1e-6f

// ---------------- scratch (no cudaMalloc allowed) ----------------
__device__ __half g_qx[MTOK*DD];
__device__ __half g_kx[MTOK*DD];
__device__ __half g_vx[MTOK*DD];
__device__ __half g_og[MTOK*DD];
__device__ __half g_wq[DD*DD];
__device__ __half g_wk[DD*DD];
__device__ __half g_wv[DD*DD];
__device__ __half g_wo[DD*DD];
__device__ float g_Q [MTOK*DD];
__device__ float g_K [MTOK*DD];
__device__ float g_V [MTOK*DD];
__device__ float g_alpha[MTOK*DD];
__device__ float g_O [MTOK*DD];
__device__ float g_hidA[MTOK*RR];
__device__ float g_hidG[MTOK*RR];
__device__ float g_beta[MTOK*HH];
__device__ float g_gate[MTOK*HH];

__device__ __forceinline__ float sigmoidf_(float v){ return 1.0f/(1.0f+expf(-v)); }
__device__ __forceinline__ float siluf_(float v){ return v/(1.0f+expf(-v)); }

// ---------------- PTX helpers (baseline ISA only; NO sm_100a features) -------------
__device__ __forceinline__ uint32_t smem_u32(const void* p){
    uint32_t a;
    asm("{ .reg .u64 t; cvta.to.shared.u64 t, %1; cvt.u32.u64 %0, t; }" : "=r"(a) : "l"(p));
    return a;
}
#define CP_COMMIT() asm volatile("cp.async.commit_group;" ::: "memory")
#define CP_WAIT1()  asm volatile("cp.async.wait_group 1;" ::: "memory")
__device__ __forceinline__ void cp16(uint32_t dst, const void* src){
    asm volatile("cp.async.cg.shared.global [%0], [%1], 16;" :: "r"(dst), "l"(src) : "memory");
}
__device__ __forceinline__ void ldm4(uint32_t* r, uint32_t addr){
    asm volatile("ldmatrix.sync.aligned.m8n8.x4.shared.b16 {%0,%1,%2,%3}, [%4];"
        : "=r"(r[0]), "=r"(r[1]), "=r"(r[2]), "=r"(r[3]) : "r"(addr));
}
__device__ __forceinline__ void mma16816(float* d, const uint32_t* a, const uint32_t* b){
    asm volatile("mma.sync.aligned.m16n8k16.row.col.f32.f16.f16.f32 "
        "{%0,%1,%2,%3}, {%4,%5,%6,%7}, {%8,%9}, {%0,%1,%2,%3};"
        : "+f"(d[0]), "+f"(d[1]), "+f"(d[2]), "+f"(d[3])
        : "r"(a[0]), "r"(a[1]), "r"(a[2]), "r"(a[3]), "r"(b[0]), "r"(b[1]));
}

// ---------------- conv + SiLU -> fp16 ----------------
__global__ void conv_silu_f16(const float* __restrict__ x,
                              const float* __restrict__ wq, const float* __restrict__ bq,
                              const float* __restrict__ wk, const float* __restrict__ bk,
                              const float* __restrict__ wv, const float* __restrict__ bv)
{
    int idx = blockIdx.x*blockDim.x + threadIdx.x;
    if (idx >= MTOK*DD) return;
    int d = idx % DD;
    int t = (idx / DD) % TT;
    int b = idx / (DD*TT);

    float xs[KSZ];
#pragma unroll
    for (int j = 0; j < KSZ; j++) {
        int tt = t - (KSZ-1) + j;
        xs[j] = (tt >= 0) ? x[((size_t)b*TT + tt)*DD + d] : 0.0f;
    }
    float aq = bq[d], ak = bk[d], av = bv[d];
#pragma unroll
    for (int j = 0; j < KSZ; j++) {
        aq = fmaf(xs[j], wq[d*KSZ + j], aq);
        ak = fmaf(xs[j], wk[d*KSZ + j], ak);
        av = fmaf(xs[j], wv[d*KSZ + j], av);
    }
    g_qx[idx] = __float2half_rn(siluf_(aq));
    g_kx[idx] = __float2half_rn(siluf_(ak));
    g_vx[idx] = __float2half_rn(siluf_(av));
}

// ---------------- 4 weights: [K,N] f32 -> [N,K] fp16 (one launch) ------------------
__global__ void wsplit_all(const float* __restrict__ W0, __half* __restrict__ H0,
                           const float* __restrict__ W1, __half* __restrict__ H1,
                           const float* __restrict__ W2, __half* __restrict__ H2,
                           const float* __restrict__ W3, __half* __restrict__ H3)
{
    const float* W; __half* Th;
    switch (blockIdx.z) {
        case 0: W = W0; Th = H0; break;
        case 1: W = W1; Th = H1; break;
        case 2: W = W2; Th = H2; break;
        default: W = W3; Th = H3; break;
    }
    __shared__ float tile[32][33];
    int k = blockIdx.y*32 + threadIdx.y;
    int n = blockIdx.x*32 + threadIdx.x;
    tile[threadIdx.y][threadIdx.x] = W[(size_t)k*DD + n];
    __syncthreads();
    int n2 = blockIdx.x*32 + threadIdx.y;
    int k2 = blockIdx.y*32 + threadIdx.x;
    Th[(size_t)n2*DD + k2] = __float2half_rn(tile[threadIdx.x][threadIdx.y]);
}

// ---------------- HMMA fp16 single-pass GEMM core ----------------------------------
#define STAGES 3
#define AROWB 80
#define STAGE_A_BYTES (128*AROWB)
#define STAGE_BYTES   (2*STAGE_A_BYTES)
#define HG_SMEM       (STAGES*STAGE_BYTES)   // 61440
#define HG_NIT 32

__device__ __forceinline__ void hgemm_body(
    const __half* __restrict__ Ap, const __half* __restrict__ Bp,
    const float* __restrict__ bias, float* __restrict__ C, int N_,
    bool do_l2, char* smem, int m0, int n0)
{
    uint32_t sb = smem_u32(smem);
    const int tid = threadIdx.x;
    const int wid = tid >> 5, lane = tid & 31;
    const int warp_m = wid >> 2, warp_n = wid & 3;

    float acc[4][4][4];
#pragma unroll
    for (int i = 0; i < 4; i++)
#pragma unroll
        for (int j = 0; j < 4; j++)
#pragma unroll
            for (int k = 0; k < 4; k++) acc[i][j][k] = 0.0f;

    const int lrow = tid >> 1;
    const int lcb  = (tid & 1) * 2;

    auto load_stage = [&](int it) {
        int kk = it << 5;
        uint32_t st = sb + (uint32_t)(it % STAGES) * STAGE_BYTES;
        const __half* ga = Ap + (size_t)(m0 + lrow)*DD + kk + lcb*8;
        uint32_t da = st + lrow*AROWB + lcb*16;
        cp16(da,      ga);
        cp16(da + 16, ga + 8);
        const __half* gb = Bp + (size_t)(n0 + lrow)*DD + kk + lcb*8;
        uint32_t db = st + STAGE_A_BYTES + lrow*AROWB + lcb*16;
        cp16(db,      gb);
        cp16(db + 16, gb + 8);
        CP_COMMIT();
    };

    load_stage(0); load_stage(1);

    const uint32_t a_row = warp_m*64 + (lane & 15);
    const uint32_t a_col = (lane >> 4) * 16;
    const uint32_t b_row = warp_n*32 + (lane & 7) + ((lane >> 4) & 1) * 8;
    const uint32_t b_col = ((lane >> 3) & 1) * 16;

    for (int i = 0; i < HG_NIT; i++) {
        CP_WAIT1();
        __syncthreads();
        int j = i + 2;
        if (j < HG_NIT) load_stage(j); else CP_COMMIT();

        uint32_t st = sb + (uint32_t)(i % STAGES) * STAGE_BYTES;
#pragma unroll
        for (int ks = 0; ks < 2; ks++) {
            uint32_t afr[4][4], bfr[2][4];
            uint32_t abase = st + a_row*AROWB + ks*32 + a_col;
#pragma unroll
            for (int mf = 0; mf < 4; mf++) ldm4(afr[mf], abase + mf*(16*AROWB));
            uint32_t bbase = st + STAGE_A_BYTES + b_row*AROWB + ks*32 + b_col;
#pragma unroll
            for (int np = 0; np < 2; np++) ldm4(bfr[np], bbase + np*(16*AROWB));
#pragma unroll
            for (int mf = 0; mf < 4; mf++)
#pragma unroll
                for (int nf = 0; nf < 4; nf++)
                    mma16816(acc[mf][nf], afr[mf], &bfr[nf >> 1][(nf & 1) * 2]);
        }
    }

    const int trow = lane >> 2, tcol = (lane & 3) * 2;

#pragma unroll
    for (int nf = 0; nf < 4; nf++) {
        int c = n0 + warp_n*32 + nf*8 + tcol;
        float b0 = bias[c], b1 = bias[c+1];
#pragma unroll
        for (int mf = 0; mf < 4; mf++) {
            acc[mf][nf][0] += b0; acc[mf][nf][1] += b1;
            acc[mf][nf][2] += b0; acc[mf][nf][3] += b1;
        }
    }

    if (do_l2) {
        float rs[8];
#pragma unroll
        for (int mf = 0; mf < 4; mf++) {
            float s0 = 0.f, s1 = 0.f;
#pragma unroll
            for (int nf = 0; nf < 4; nf++) {
                s0 = fmaf(acc[mf][nf][0], acc[mf][nf][0], s0);
                s0 = fmaf(acc[mf][nf][1], acc[mf][nf][1], s0);
                s1 = fmaf(acc[mf][nf][2], acc[mf][nf][2], s1);
                s1 = fmaf(acc[mf][nf][3], acc[mf][nf][3], s1);
            }
            rs[mf*2]   = s0;
            rs[mf*2+1] = s1;
        }
#pragma unroll
        for (int r = 0; r < 8; r++) {
            rs[r] += __shfl_xor_sync(0xFFFFFFFFu, rs[r], 1);
            rs[r] += __shfl_xor_sync(0xFFFFFFFFu, rs[r], 2);
        }
        __syncthreads();
        float* sred = reinterpret_cast<float*>(smem);   // [4][128]
        if ((lane & 3) == 0) {
#pragma unroll
            for (int mf = 0; mf < 4; mf++) {
                int r = warp_m*64 + mf*16 + trow;
                sred[warp_n*128 + r]     = rs[mf*2];
                sred[warp_n*128 + r + 8] = rs[mf*2+1];
            }
        }
        __syncthreads();
        const int gp = (warp_n >> 1) * 2;
#pragma unroll
        for (int mf = 0; mf < 4; mf++) {
#pragma unroll
            for (int half = 0; half < 2; half++) {
                int r = warp_m*64 + mf*16 + trow + half*8;
                float tot = sred[gp*128 + r] + sred[(gp+1)*128 + r];
                float rn = rsqrtf(fmaxf(tot, EPSF));
                acc[mf][0][half*2]   *= rn; acc[mf][0][half*2+1] *= rn;
                acc[mf][1][half*2]   *= rn; acc[mf][1][half*2+1] *= rn;
                acc[mf][2][half*2]   *= rn; acc[mf][2][half*2+1] *= rn;
                acc[mf][3][half*2]   *= rn; acc[mf][3][half*2+1] *= rn;
            }
        }
    }

#pragma unroll
    for (int mf = 0; mf < 4; mf++) {
        int r = m0 + warp_m*64 + mf*16 + trow;
#pragma unroll
        for (int nf = 0; nf < 4; nf++) {
            int c = n0 + warp_n*32 + nf*8 + tcol;
            float* p0 = C + (size_t)r*N_ + c;
            float* p1 = C + (size_t)(r+8)*N_ + c;
            p0[0] = acc[mf][nf][0]; p0[1] = acc[mf][nf][1];
            p1[0] = acc[mf][nf][2]; p1[1] = acc[mf][nf][3];
        }
    }
}

// single-matrix wrapper (output GEMM)
__global__ __launch_bounds__(256)
void hgemm1(const __half* __restrict__ Ap, const __half* __restrict__ Bp,
            const float* __restrict__ bias, float* __restrict__ C, int N_)
{
    extern __shared__ char smem[];
    hgemm_body(Ap, Bp, bias, C, N_, false, smem, blockIdx.y << 7, blockIdx.x << 7);
}

// z-batched QKV GEMM: z=0 Q (L2), z=1 K (L2), z=2 V
__global__ __launch_bounds__(256)
void hgemm_qkv(const __half* __restrict__ qx, const __half* __restrict__ kx,
               const __half* __restrict__ vx,
               const __half* __restrict__ wq, const __half* __restrict__ wk,
               const __half* __restrict__ wv,
               const float* __restrict__ bq, const float* __restrict__ bk,
               const float* __restrict__ bv,
               float* __restrict__ Qp, float* __restrict__ Kp, float* __restrict__ Vp)
{
    extern __shared__ char smem[];
    const __half *Ap, *Bp; const float* bias; float* C; bool do_l2;
    switch (blockIdx.z) {
        case 0:  Ap = qx; Bp = wq; bias = bq; C = Qp; do_l2 = true;  break;
        case 1:  Ap = kx; Bp = wk; bias = bk; C = Kp; do_l2 = true;  break;
        default: Ap = vx; Bp = wv; bias = bv; C = Vp; do_l2 = false; break;
    }
    hgemm_body(Ap, Bp, bias, C, DD, do_l2, smem, blockIdx.y << 7, blockIdx.x << 7);
}

// ---------------- fp32 SGEMM 128x128 (alpha-up, K=64, sigmoid) ---------------------
template<int ACT>
__global__ __launch_bounds__(256)
void gemm128(const float* __restrict__ A, const float* __restrict__ W,
             const float* __restrict__ bias, float* __restrict__ C,
             int M, int N, int K)
{
    __shared__ float As[8][128];
    __shared__ float Bs[8][128];

    const int tid = threadIdx.x;
    const int m0 = blockIdx.y * 128;
    const int n0 = blockIdx.x * 128;
    const int ty = tid >> 4;
    const int tx = tid & 15;
    const int arow = tid >> 1;
    const int ak   = (tid & 1) * 4;
    const int brow = tid >> 5;
    const int bcol = (tid & 31) * 4;

    float acc[8][8];
#pragma unroll
    for (int i = 0; i < 8; i++)
#pragma unroll
        for (int j = 0; j < 8; j++) acc[i][j] = 0.0f;

    for (int k0 = 0; k0 < K; k0 += 8) {
        float4 a4 = *reinterpret_cast<const float4*>(&A[(size_t)(m0 + arow)*K + k0 + ak]);
        float4 b4 = *reinterpret_cast<const float4*>(&W[(size_t)(k0 + brow)*N + n0 + bcol]);
        __syncthreads();
        As[ak+0][arow] = a4.x; As[ak+1][arow] = a4.y;
        As[ak+2][arow] = a4.z; As[ak+3][arow] = a4.w;
        *reinterpret_cast<float4*>(&Bs[brow][bcol]) = b4;
        __syncthreads();
#pragma unroll
        for (int k = 0; k < 8; k++) {
            float ra[8], rb[8];
#pragma unroll
            for (int i = 0; i < 8; i++) ra[i] = As[k][ty*8 + i];
#pragma unroll
            for (int i = 0; i < 8; i++) rb[i] = Bs[k][tx*8 + i];
#pragma unroll
            for (int i = 0; i < 8; i++)
#pragma unroll
                for (int j = 0; j < 8; j++)
                    acc[i][j] = fmaf(ra[i], rb[j], acc[i][j]);
        }
    }

#pragma unroll
    for (int i = 0; i < 8; i++) {
        int m = m0 + ty*8 + i;
#pragma unroll
        for (int j = 0; j < 8; j++) {
            int n = n0 + tx*8 + j;
            float c = acc[i][j] + bias[n];
            if (ACT == 1) c = siluf_(c);
            else if (ACT == 2) c = sigmoidf_(c);
            C[(size_t)m*N + n] = c;
        }
    }
}

// ---------------- fused x-projections: hA (silu) | hG (silu) | beta (sigmoid) ------
__global__ __launch_bounds__(256)
void prep144(const float* __restrict__ x,
             const float* __restrict__ W_ad, const float* __restrict__ b_ad,
             const float* __restrict__ W_gd, const float* __restrict__ b_gd,
             const float* __restrict__ W_bt, const float* __restrict__ b_bt,
             float* __restrict__ hA, float* __restrict__ hG, float* __restrict__ Bt)
{
    __shared__ float Xs[16][68];
    __shared__ float Ws[16][144];

    const int tid = threadIdx.x;
    const int m0 = blockIdx.x * 64;
    const int ty = tid >> 4, tx = tid & 15;

    float acc[4][9];
#pragma unroll
    for (int i = 0; i < 4; i++)
#pragma unroll
        for (int j = 0; j < 9; j++) acc[i][j] = 0.0f;

    const int xrow = tid >> 2, xk = (tid & 3) * 4;
    const int wk = tid >> 4, wc = tid & 15;

    for (int k0 = 0; k0 < DD; k0 += 16) {
        __syncthreads();
        float4 xv = *reinterpret_cast<const float4*>(&x[(size_t)(m0 + xrow)*DD + k0 + xk]);
        Xs[xk+0][xrow] = xv.x; Xs[xk+1][xrow] = xv.y;
        Xs[xk+2][xrow] = xv.z; Xs[xk+3][xrow] = xv.w;
#pragma unroll
        for (int j = 0; j < 9; j++) {
            int c = wc + j*16;
            float w;
            if (c < 64)       w = W_ad[(size_t)(k0 + wk)*64 + c];
            else if (c < 128) w = W_gd[(size_t)(k0 + wk)*64 + (c - 64)];
            else              w = W_bt[(size_t)(k0 + wk)*16 + (c - 128)];
            Ws[wk][c] = w;
        }
        __syncthreads();
#pragma unroll
        for (int k = 0; k < 16; k++) {
            float ra[4], rb[9];
#pragma unroll
            for (int i = 0; i < 4; i++) ra[i] = Xs[k][ty*4 + i];
#pragma unroll
            for (int j = 0; j < 9; j++) rb[j] = Ws[k][tx + j*16];
#pragma unroll
            for (int i = 0; i < 4; i++)
#pragma unroll
                for (int j = 0; j < 9; j++)
                    acc[i][j] = fmaf(ra[i], rb[j], acc[i][j]);
        }
    }

#pragma unroll
    for (int i = 0; i < 4; i++) {
        int m = m0 + ty*4 + i;
#pragma unroll
        for (int j = 0; j < 9; j++) {
            int c = tx + j*16;
            float v = acc[i][j];
            if (c < 64)       hA[(size_t)m*64 + c]        = siluf_(v + b_ad[c]);
            else if (c < 128) hG[(size_t)m*64 + (c-64)]   = siluf_(v + b_gd[c-64]);
            else              Bt[(size_t)m*16 + (c-128)]  = sigmoidf_(v + b_bt[c-128]);
        }
    }
}

// ---------------- gate-up: gate = sigmoid(hidG @ W_gu + b_gu) ----------------------
__global__ __launch_bounds__(256)
void gateup(const float* __restrict__ hG, const float* __restrict__ W_gu,
            const float* __restrict__ b_gu, float* __restrict__ Gt)
{
    int gidx = blockIdx.x*256 + threadIdx.x;
    int m = gidx >> 4, h = gidx & 15;
    const float* row = hG + (size_t)m*64;
    float s = b_gu[h];
#pragma unroll 8
    for (int i = 0; i < 64; i++) s = fmaf(row[i], W_gu[i*16 + h], s);
    Gt[gidx] = sigmoidf_(s);
}

// ---------------- gated delta-rule scan v8 (R10/R12 best): 256 blk, 4 rows/thread --
__global__ __launch_bounds__(256, 2)
void scan_kernel8(const float* __restrict__ Q, const float* __restrict__ K,
                  const float* __restrict__ V, const float* __restrict__ A,
                  const float* __restrict__ Beta,
                  float* __restrict__ O, float* __restrict__ Sout)
{
    const int blk = blockIdx.x;           // 0..255
    const int bh  = blk >> 2, qtr = blk & 3;
    const int b = bh / HH, h = bh % HH;
    const int tid = threadIdx.x;
    const int e   = tid & 15;             // 16 row-groups of 4
    const int col = qtr*16 + (tid >> 4);  // 0..63
    const int r0  = e * 4;

    const size_t base  = ((size_t)b*TT)*DD + (size_t)h*64;
    const size_t bbase = (size_t)b*TT*HH + h;

    float S[4];
#pragma unroll
    for (int i = 0; i < 4; i++) S[i] = 0.0f;

    float4 kb[4], ab[4], qb[4];
    float  vb[4], bbuf[4];

#define SCAN_LOAD(t_, s_) do { \
    kb[s_] = *reinterpret_cast<const float4*>(K + base + (size_t)(t_)*DD + r0); \
    ab[s_] = *reinterpret_cast<const float4*>(A + base + (size_t)(t_)*DD + r0); \
    qb[s_] = *reinterpret_cast<const float4*>(Q + base + (size_t)(t_)*DD + r0); \
    vb[s_]   = V[base + (size_t)(t_)*DD + col]; \
    bbuf[s_] = Beta[bbase + (size_t)(t_)*HH]; \
} while(0)

    SCAN_LOAD(0, 0); SCAN_LOAD(1, 1); SCAN_LOAD(2, 2);

    for (int g = 0; g < TT/8; g++) {
        float ob[8];
#pragma unroll
        for (int u = 0; u < 8; u++) {
            const int t = g*8 + u;
            const int s = u & 3;
            if (t + 3 < TT) SCAN_LOAD(t + 3, (u + 3) & 3);

            float k_[4], a_[4], q_[4];
            *reinterpret_cast<float4*>(k_) = kb[s];
            *reinterpret_cast<float4*>(a_) = ab[s];
            *reinterpret_cast<float4*>(q_) = qb[s];
            const float vv = vb[s];
            const float bt = bbuf[s];

            float p0 = 0.f, p1 = 0.f;
            S[0] *= a_[0]; p0 = fmaf(k_[0], S[0], p0);
            S[1] *= a_[1]; p1 = fmaf(k_[1], S[1], p1);
            S[2] *= a_[2]; p0 = fmaf(k_[2], S[2], p0);
            S[3] *= a_[3]; p1 = fmaf(k_[3], S[3], p1);
            float p = p0 + p1;
            p += __shfl_xor_sync(0xFFFFFFFFu, p, 1);
            p += __shfl_xor_sync(0xFFFFFFFFu, p, 2);
            p += __shfl_xor_sync(0xFFFFFFFFu, p, 4);
            p += __shfl_xor_sync(0xFFFFFFFFu, p, 8);

            float c = bt * (vv - p);

            float o0 = 0.f, o1 = 0.f;
            S[0] = fmaf(k_[0], c, S[0]); o0 = fmaf(S[0], q_[0], o0);
            S[1] = fmaf(k_[1], c, S[1]); o1 = fmaf(S[1], q_[1], o1);
            S[2] = fmaf(k_[2], c, S[2]); o0 = fmaf(S[2], q_[2], o0);
            S[3] = fmaf(k_[3], c, S[3]); o1 = fmaf(S[3], q_[3], o1);
            ob[u] = o0 + o1;
        }

#pragma unroll
        for (int r = 1; r <= 8; r <<= 1) {
            float t0 = __shfl_xor_sync(0xFFFFFFFFu, ob[0], r);
            float t1 = __shfl_xor_sync(0xFFFFFFFFu, ob[1], r);
            float t2 = __shfl_xor_sync(0xFFFFFFFFu, ob[2], r);
            float t3 = __shfl_xor_sync(0xFFFFFFFFu, ob[3], r);
            float t4 = __shfl_xor_sync(0xFFFFFFFFu, ob[4], r);
            float t5 = __shfl_xor_sync(0xFFFFFFFFu, ob[5], r);
            float t6 = __shfl_xor_sync(0xFFFFFFFFu, ob[6], r);
            float t7 = __shfl_xor_sync(0xFFFFFFFFu, ob[7], r);
            ob[0] += t0; ob[1] += t1; ob[2] += t2; ob[3] += t3;
            ob[4] += t4; ob[5] += t5; ob[6] += t6; ob[7] += t7;
        }
        if (e == 0) {
            const int tg = g * 8;
#pragma unroll
            for (int u = 0; u < 8; u++)
                O[base + (size_t)(tg + u)*DD + col] = ob[u];
        }
    }
#undef SCAN_LOAD

#pragma unroll
    for (int i = 0; i < 4; i++)
        Sout[(size_t)bh*DKV*DKV + (size_t)(r0 + i)*DKV + col] = S[i];
}

// ---------------- headwise RMSNorm + gate -> fp16 ----------------------------------
__global__ __launch_bounds__(256)
void normgate_f16(const float* __restrict__ O, const float* __restrict__ rms_w,
                  const float* __restrict__ gate, __half* __restrict__ og)
{
    int row = blockIdx.x*4 + (threadIdx.x >> 6);
    int j   = threadIdx.x & 63;
    int h   = row % HH;

    float v = O[(size_t)row*64 + j];
    float ss = v*v;
#pragma unroll
    for (int o = 16; o; o >>= 1) ss += __shfl_xor_sync(0xFFFFFFFFu, ss, o);

    __shared__ float part[8];
    if ((threadIdx.x & 31) == 0) part[threadIdx.x >> 5] = ss;
    __syncthreads();
    int w0 = (threadIdx.x >> 6) * 2;
    float tot = part[w0] + part[w0 + 1];

    float rn  = rsqrtf(tot * (1.0f/64.0f) + EPSF);
    og[(size_t)row*64 + j] = __float2half_rn(v * rn * rms_w[h*64 + j] * gate[row]);
}

// ---------------- launch (multi-stream fork/join, graph-capturable) ----------------
extern "C" void kernel_launch(void* const* d_in, const int* in_sizes, int n_in,
                              void* d_out, int out_size)
{
    const float* x       = (const float*)d_in[0];
    const float* conv_qw = (const float*)d_in[1];
    const float* conv_qb = (const float*)d_in[2];
    const float* conv_kw = (const float*)d_in[3];
    const float* conv_kb = (const float*)d_in[4];
    const float* conv_vw = (const float*)d_in[5];
    const float* conv_vb = (const float*)d_in[6];
    const float* Wq      = (const float*)d_in[7];
    const float* bq      = (const float*)d_in[8];
    const float* Wk      = (const float*)d_in[9];
    const float* bk      = (const float*)d_in[10];
    const float* Wv      = (const float*)d_in[11];
    const float* bv      = (const float*)d_in[12];
    const float* W_ad    = (const float*)d_in[13];
    const float* b_ad    = (const float*)d_in[14];
    const float* W_au    = (const float*)d_in[15];
    const float* b_au    = (const float*)d_in[16];
    const float* W_beta  = (const float*)d_in[17];
    const float* b_beta  = (const float*)d_in[18];
    const float* rms_w   = (const float*)d_in[19];
    const float* W_gd    = (const float*)d_in[20];
    const float* b_gd    = (const float*)d_in[21];
    const float* W_gu    = (const float*)d_in[22];
    const float* b_gu    = (const float*)d_in[23];
    const float* Wo      = (const float*)d_in[24];
    const float* bo      = (const float*)d_in[25];

    float* out = (float*)d_out;
    float* y = out;
    const size_t y_elems = (size_t)MTOK * DD;
    const size_t s_elems = (size_t)BH * DKV * DKV;
    float* Sout = out + ((size_t)out_size >= y_elems + s_elems
                         ? (size_t)out_size - s_elems : y_elems);

    float *Qp, *Kp, *Vp, *Al, *Op, *hA, *hG, *Bt, *Gt;
    cudaGetSymbolAddress((void**)&Qp, g_Q);
    cudaGetSymbolAddress((void**)&Kp, g_K);
    cudaGetSymbolAddress((void**)&Vp, g_V);
    cudaGetSymbolAddress((void**)&Al, g_alpha);
    cudaGetSymbolAddress((void**)&Op, g_O);
    cudaGetSymbolAddress((void**)&hA, g_hidA);
    cudaGetSymbolAddress((void**)&hG, g_hidG);
    cudaGetSymbolAddress((void**)&Bt, g_beta);
    cudaGetSymbolAddress((void**)&Gt, g_gate);

    __half *qx,*kx,*vx,*og,*wq,*wk,*wv,*wo;
    cudaGetSymbolAddress((void**)&qx, g_qx);
    cudaGetSymbolAddress((void**)&kx, g_kx);
    cudaGetSymbolAddress((void**)&vx, g_vx);
    cudaGetSymbolAddress((void**)&og, g_og);
    cudaGetSymbolAddress((void**)&wq, g_wq);
    cudaGetSymbolAddress((void**)&wk, g_wk);
    cudaGetSymbolAddress((void**)&wv, g_wv);
    cudaGetSymbolAddress((void**)&wo, g_wo);

    cudaFuncSetAttribute(hgemm1,    cudaFuncAttributeMaxDynamicSharedMemorySize, HG_SMEM);
    cudaFuncSetAttribute(hgemm_qkv, cudaFuncAttributeMaxDynamicSharedMemorySize, HG_SMEM);

    static cudaStream_t s1 = nullptr, s2 = nullptr;
    static cudaEvent_t evRoot = nullptr, evW = nullptr, evAlpha = nullptr, evGate = nullptr;
    if (!s1) {
        cudaStreamCreateWithFlags(&s1, cudaStreamNonBlocking);
        cudaStreamCreateWithFlags(&s2, cudaStreamNonBlocking);
        cudaEventCreateWithFlags(&evRoot,  cudaEventDisableTiming);
        cudaEventCreateWithFlags(&evW,     cudaEventDisableTiming);
        cudaEventCreateWithFlags(&evAlpha, cudaEventDisableTiming);
        cudaEventCreateWithFlags(&evGate,  cudaEventDisableTiming);
    }

    cudaEventRecord(evRoot, 0);
    cudaStreamWaitEvent(s1, evRoot, 0);
    cudaStreamWaitEvent(s2, evRoot, 0);

    dim3 wgrid(DD/32, DD/32, 4), wblk(32, 32);
    wsplit_all<<<wgrid, wblk, 0, s1>>>(Wq, wq, Wk, wk, Wv, wv, Wo, wo);
    cudaEventRecord(evW, s1);

    prep144<<<MTOK/64, 256, 0, s2>>>(x, W_ad, b_ad, W_gd, b_gd, W_beta, b_beta, hA, hG, Bt);
    gemm128<2><<<dim3(DD/128, MTOK/128), 256, 0, s2>>>(hA, W_au, b_au, Al, MTOK, DD, RR);
    cudaEventRecord(evAlpha, s2);
    gateup<<<MTOK*HH/256, 256, 0, s2>>>(hG, W_gu, b_gu, Gt);
    cudaEventRecord(evGate, s2);

    conv_silu_f16<<<(MTOK*DD + 255)/256, 256>>>(x, conv_qw, conv_qb,
                                                conv_kw, conv_kb, conv_vw, conv_vb);
    cudaStreamWaitEvent(0, evW, 0);

    // Q/K/V projections in ONE z-batched launch (1536 CTAs -> small tail)
    dim3 tgrid3(DD/128, MTOK/128, 3);
    hgemm_qkv<<<tgrid3, 256, HG_SMEM>>>(qx, kx, vx, wq, wk, wv, bq, bk, bv, Qp, Kp, Vp);

    cudaStreamWaitEvent(0, evAlpha, 0);
    scan_kernel8<<<4*BH, 256>>>(Qp, Kp, Vp, Al, Bt, Op, Sout);

    cudaStreamWaitEvent(0, evGate, 0);
    normgate_f16<<<(MTOK*HH)/4, 256>>>(Op, rms_w, Gt, og);
    dim3 tgrid(DD/128, MTOK/128);
    hgemm1<<<tgrid, 256, HG_SMEM>>>(og, wo, bo, y, DD);
}